// round 14
// baseline (speedup 1.0000x reference)
#include <cuda_runtime.h>
#include <math.h>

#define BB 4
#define TT 2048
#define CC 48
#define DD 512
#define LL 16
#define KK 9
#define CSZ 15
#define NTR 15
#define NCAND 45
#define WINLEN 19
#define TP8 (TT + 8)
#define NB45 96

// ------------------- device scratch (static, no allocs) -------------------
__device__ float g_prob[BB * TT * CC];
__device__ float g_lse[BB * TT];
__device__ float g_ent2[BB * TT];
__device__ float g_cross[BB * 8 * TP8];   // d = 1..8 (d=0 analytic)
__device__ float g_score[BB * TT];
__device__ int   g_bdy[BB * NTR];
__device__ float g_fr32[BB * 8];
__device__ float g_glc_part[BB * LL];
__device__ float g_n2i[BB * CC];          // 10 / ||tok_row||  (TEMP folded)
__device__ int   g_ticket;                // zero-init; reset by last block
__device__ int   g_cnt45;                 // zero-init; reset by releaser
__device__ int   g_gen45;                 // zero-init; monotonic across replays

// 96-block spin barrier (all blocks resident by construction)
__device__ __forceinline__ void bar45() {
    __syncthreads();
    if (threadIdx.x == 0) {
        __threadfence();
        int gen = *((volatile int*)&g_gen45);
        if (atomicAdd(&g_cnt45, 1) == NB45 - 1) {
            g_cnt45 = 0;
            __threadfence();
            atomicExch(&g_gen45, gen + 1);
        } else {
            while (*((volatile int*)&g_gen45) == gen) __nanosleep(64);
        }
        __threadfence();
    }
    __syncthreads();
}

// order-preserving float -> uint32 (suppressed marker 0 is minimal)
__device__ __forceinline__ unsigned f2sortable(float f) {
    unsigned u = __float_as_uint(f);
    return (u & 0x80000000u) ? ~u : (u | 0x80000000u);
}

__device__ __forceinline__ unsigned long long pk2f(float c) {
    unsigned long long r;
    asm("mov.b64 %0, {%1,%1};" : "=l"(r) : "f"(c));
    return r;
}

// Cephes log2 on two values via packed f32x2 FMA pipe
// Finite output for zero/denormal input (returns ~ -127), so callers may
// rely on p * fast_log2(p) == 0 when p == 0.
__device__ __forceinline__ float2 fast_log2_x2(float x0, float x1) {
    unsigned u0 = __float_as_uint(x0), u1 = __float_as_uint(x1);
    int e0 = (int)(u0 >> 23) - 127, e1 = (int)(u1 >> 23) - 127;
    float m0 = __uint_as_float((u0 & 0x007fffffu) | 0x3f800000u);
    float m1 = __uint_as_float((u1 & 0x007fffffu) | 0x3f800000u);
    if (m0 > 1.4142135f) { m0 *= 0.5f; e0 += 1; }
    if (m1 > 1.4142135f) { m1 *= 0.5f; e1 += 1; }
    float z0 = m0 - 1.f, z1 = m1 - 1.f;
    unsigned long long Z, Z2, P, W, Y, E, R;
    asm("mov.b64 %0, {%1,%2};" : "=l"(Z) : "f"(z0), "f"(z1));
    asm("mul.rn.f32x2 %0, %1, %1;" : "=l"(Z2) : "l"(Z));
    P = pk2f(7.0376836292e-2f);
    asm("fma.rn.f32x2 %0, %1, %2, %3;" : "=l"(P) : "l"(P), "l"(Z), "l"(pk2f(-1.1514610310e-1f)));
    asm("fma.rn.f32x2 %0, %1, %2, %3;" : "=l"(P) : "l"(P), "l"(Z), "l"(pk2f( 1.1676998740e-1f)));
    asm("fma.rn.f32x2 %0, %1, %2, %3;" : "=l"(P) : "l"(P), "l"(Z), "l"(pk2f(-1.2420140846e-1f)));
    asm("fma.rn.f32x2 %0, %1, %2, %3;" : "=l"(P) : "l"(P), "l"(Z), "l"(pk2f( 1.4249322787e-1f)));
    asm("fma.rn.f32x2 %0, %1, %2, %3;" : "=l"(P) : "l"(P), "l"(Z), "l"(pk2f(-1.6668057665e-1f)));
    asm("fma.rn.f32x2 %0, %1, %2, %3;" : "=l"(P) : "l"(P), "l"(Z), "l"(pk2f( 2.0000714765e-1f)));
    asm("fma.rn.f32x2 %0, %1, %2, %3;" : "=l"(P) : "l"(P), "l"(Z), "l"(pk2f(-2.4999993993e-1f)));
    asm("fma.rn.f32x2 %0, %1, %2, %3;" : "=l"(P) : "l"(P), "l"(Z), "l"(pk2f( 3.3333331174e-1f)));
    asm("fma.rn.f32x2 %0, %1, %2, %3;" : "=l"(W) : "l"(Z2), "l"(pk2f(-0.5f)), "l"(Z));
    asm("mul.rn.f32x2 %0, %1, %2;" : "=l"(P) : "l"(P), "l"(Z));
    asm("fma.rn.f32x2 %0, %1, %2, %3;" : "=l"(Y) : "l"(P), "l"(Z2), "l"(W));
    float ef0 = (float)e0, ef1 = (float)e1;
    asm("mov.b64 %0, {%1,%2};" : "=l"(E) : "f"(ef0), "f"(ef1));
    asm("fma.rn.f32x2 %0, %1, %2, %3;" : "=l"(R) : "l"(Y), "l"(pk2f(1.44269504089f)), "l"(E));
    float r0, r1;
    asm("mov.b64 {%0,%1}, %2;" : "=f"(r0), "=f"(r1) : "l"(R));
    return make_float2(r0, r1);
}

__device__ __forceinline__ float log_sigmoid_f(float x) {
    return (x >= 0.f) ? -log1pf(__expf(-x)) : x - log1pf(__expf(x));
}

// ------------------- K1: softmax rows + lse + ent2, plus token norms -------
// entropy logs dual-piped: lanes<16 pack (p0,p1) through the FMA-pipe poly,
// lanes>=16 use MUFU -> MUFU logs/row drop 48 -> 16.
__global__ void k1_softmax(const float* __restrict__ fr,
                           const float* __restrict__ feat) {
    if (blockIdx.x >= (BB * TT) / 8) {
        int b = blockIdx.x - (BB * TT) / 8;
        int w = threadIdx.x >> 5;
        int lane = threadIdx.x & 31;
        const float4* tokb4 = (const float4*)(feat + (size_t)b * (CC + TT) * DD);
        #pragma unroll
        for (int jj = 0; jj < 6; jj++) {
            int j = w * 6 + jj;
            const float4* tkr = tokb4 + (size_t)j * 128;
            float n2 = 0.f;
            #pragma unroll
            for (int kk = 0; kk < 4; kk++) {
                float4 tv = tkr[lane + 32 * kk];
                n2 += tv.x * tv.x + tv.y * tv.y + tv.z * tv.z + tv.w * tv.w;
            }
            #pragma unroll
            for (int o = 16; o > 0; o >>= 1) n2 += __shfl_xor_sync(0xffffffffu, n2, o);
            if (lane == 0) g_n2i[b * CC + j] = 10.f / fmaxf(sqrtf(n2), 1e-12f);
        }
        return;
    }
    int gw = (blockIdx.x * blockDim.x + threadIdx.x) >> 5;
    int lane = threadIdx.x & 31;
    const float* row = fr + (size_t)gw * CC;
    float x0 = row[lane];
    float x1 = (lane < 16) ? row[lane + 32] : -INFINITY;
    float m = fmaxf(x0, x1);
    #pragma unroll
    for (int o = 16; o > 0; o >>= 1) m = fmaxf(m, __shfl_xor_sync(0xffffffffu, m, o));
    float e0 = __expf(x0 - m);
    float e1 = (lane < 16) ? __expf(x1 - m) : 0.f;
    float s = e0 + e1;
    #pragma unroll
    for (int o = 16; o > 0; o >>= 1) s += __shfl_xor_sync(0xffffffffu, s, o);
    float inv = 1.f / s;
    float p0 = e0 * inv, p1 = e1 * inv;
    float ent;
    if (lane < 16) {
        float2 lg = fast_log2_x2(p0, p1);     // finite at 0; 0*lg == 0
        ent = p0 * lg.x + p1 * lg.y;
    } else {
        ent = (p0 > 0.f) ? p0 * __log2f(p0) : 0.f;
    }
    #pragma unroll
    for (int o = 16; o > 0; o >>= 1) ent += __shfl_xor_sync(0xffffffffu, ent, o);
    float* pr = g_prob + (size_t)gw * CC;
    pr[lane] = p0;
    if (lane < 16) pr[lane + 32] = p1;
    if (lane == 0) {
        g_lse[gw] = m + __logf(s);
        g_ent2[gw] = ent;
    }
}

// ------------------- K2: crossD, 2 tasks per warp, float4, 3:5 pipe split --
__global__ void k2_cross() {
    int gw = (blockIdx.x * blockDim.x + threadIdx.x) >> 5;
    int lane = threadIdx.x & 31;
    int group = lane >> 4;
    int gl = lane & 15;
    cudaGridDependencySynchronize();     // PDL: wait for k1's g_prob

    int task = gw * 2 + group;
    int b = task / (8 * TP8);
    int rem = task % (8 * TP8);
    int d = rem / TP8 + 1;      // 1..8, warp-uniform
    int r4 = rem % TP8;
    int r1 = r4 - 4;
    int r2 = r1 + d;

    const float4* base = (const float4*)(g_prob + (size_t)b * TT * CC);
    float acc = 0.f;
    if (gl < 12) {
        float4 a = (r1 >= 0 && r1 < TT) ? base[r1 * 12 + gl]
                                        : make_float4(0.f, 0.f, 0.f, 0.f);
        float4 c = (r2 >= 0 && r2 < TT) ? base[r2 * 12 + gl]
                                        : make_float4(0.f, 0.f, 0.f, 0.f);
        float sv0 = a.x + c.x, sv1 = a.y + c.y;
        float sv2 = a.z + c.z, sv3 = a.w + c.w;
        float xx0 = 0.5f * sv0 + 1e-32f;
        float xx1 = 0.5f * sv1 + 1e-32f;
        float xx2 = 0.5f * sv2 + 1e-32f;
        float xx3 = 0.5f * sv3 + 1e-32f;
        float lg0, lg1, lg2, lg3;
        if (d <= 3) {              // 3:5 split: poly costs ~3.25 cyc/log vs MUFU 2
            float2 la = fast_log2_x2(xx0, xx1);
            float2 lb = fast_log2_x2(xx2, xx3);
            lg0 = la.x; lg1 = la.y; lg2 = lb.x; lg3 = lb.y;
        } else {
            lg0 = __log2f(xx0);
            lg1 = __log2f(xx1);
            lg2 = __log2f(xx2);
            lg3 = __log2f(xx3);
        }
        acc = sv0 * lg0 + sv1 * lg1 + sv2 * lg2 + sv3 * lg3;
    }
    #pragma unroll
    for (int o = 8; o > 0; o >>= 1) acc += __shfl_xor_sync(0xffffffffu, acc, o);
    if (gl == 0) g_cross[(b * 8 + (d - 1)) * TP8 + r4] = acc;
}

// ------------------- K3: boundary score per (b,t) (reduced form) -----------
__global__ void k3_score() {
    int idx = blockIdx.x * blockDim.x + threadIdx.x;
    cudaGridDependencySynchronize();     // PDL: wait for k2's g_cross
    if (idx >= BB * TT) return;
    int b = idx / TT;
    int t = idx % TT;
    float se = 0.f;
    #pragma unroll
    for (int i = 0; i < 4; i++) {
        int r = t - 4 + i;
        se += (r >= 0) ? g_ent2[b * TT + r] : 0.f;
    }
    float cs = 0.f;
    #pragma unroll
    for (int d = 1; d <= 8; d++) {
        const float* crb = g_cross + (size_t)(b * 8 + d - 1) * TP8 + t;
        #pragma unroll
        for (int i = 0; i + d <= 8; i++) {
            float w = ((i < 4) == ((i + d) < 4)) ? 2.f : -2.f;
            cs += w * crb[i];
        }
    }
    float sc = (4.f * se + cs) * (1.f / 81.f);
    if (t == 0) sc = -INFINITY;
    g_score[idx] = sc;
}

// ------------------- K45: detect (blocks 0..3) + barrier + CE/GLC/final ----
__global__ void k45(const float* __restrict__ fr_logit,
                    const int* __restrict__ transcript,
                    const float* __restrict__ feat,
                    const float* __restrict__ tok_logit,
                    const float* __restrict__ y,
                    float* __restrict__ out) {
    __shared__ __align__(16) unsigned ss[TT];
    __shared__ float sfs[TT];
    __shared__ int scand[NCAND];
    __shared__ int scand2[NCAND];
    __shared__ float scls[NTR * NCAND];
    __shared__ signed char sdir[NCAND * 31];
    __shared__ int s_tr[LL];
    __shared__ float sred[256];
    __shared__ int s_last;

    int blk = blockIdx.x;
    int tid = threadIdx.x;
    int lane = tid & 31;
    int w = tid >> 5;

    int b5 = blk / 24;
    int role = blk % 24;
    int btr = (blk < BB) ? blk : b5;
    if (tid < LL) s_tr[tid] = transcript[btr * LL + tid];
    cudaGridDependencySynchronize();       // PDL: wait for k3's g_score

    // =================== Phase 1: k4 on blocks 0..3 =========================
    if (blk < BB) {
        int b = blk;
        for (int t = tid; t < TT; t += 256) {
            float sc = g_score[b * TT + t];
            sfs[t] = sc;
            ss[t] = f2sortable(sc);
        }
        __syncthreads();

        if (tid < 32) {
            const uint4* ss4 = (const uint4*)ss;
            unsigned v0 = 0u, v1 = 0u;
            #pragma unroll
            for (int q = 0; q < 8; q++) {
                uint4 a = ss4[lane * 8 + q];
                uint4 c = ss4[(lane + 32) * 8 + q];
                v0 = max(v0, max(max(a.x, a.y), max(a.z, a.w)));
                v1 = max(v1, max(max(c.x, c.y), max(c.z, c.w)));
            }
            for (int it = 0; it < NCAND; it++) {
                unsigned loc = max(v0, v1);
                unsigned mv = __reduce_max_sync(0xffffffffu, loc);
                unsigned m0 = __ballot_sync(0xffffffffu, v0 == mv);
                unsigned m1 = __ballot_sync(0xffffffffu, v1 == mv);
                int seg = m0 ? (__ffs(m0) - 1) : (32 + __ffs(m1) - 1);
                unsigned val = ss[seg * 32 + lane];
                unsigned mk = __ballot_sync(0xffffffffu, val == mv);
                int pick = seg * 32 + (__ffs(mk) - 1);
                if (lane == 0) scand[it] = pick;

                int lo = pick - WINLEN, hi = pick + WINLEN;
                int p0 = lo + lane;
                if (p0 >= 0 && p0 < TT) ss[p0] = 0u;
                int p1 = p0 + 32;
                if (p1 <= hi && p1 < TT) ss[p1] = 0u;
                __syncwarp();

                int slo = (lo < 0 ? 0 : lo) >> 5;
                int shi = ((hi > TT - 1 ? TT - 1 : hi)) >> 5;
                int myseg = (lane >= slo && lane <= shi) ? lane
                          : ((lane + 32 >= slo && lane + 32 <= shi) ? lane + 32 : -1);
                if (myseg >= 0) {
                    const uint4* sp = (const uint4*)(ss + myseg * 32);
                    uint4 a0 = sp[0], a1 = sp[1], a2 = sp[2], a3 = sp[3];
                    uint4 a4 = sp[4], a5 = sp[5], a6 = sp[6], a7 = sp[7];
                    unsigned t0 = max(max(a0.x, a0.y), max(a0.z, a0.w));
                    unsigned t1 = max(max(a1.x, a1.y), max(a1.z, a1.w));
                    unsigned t2 = max(max(a2.x, a2.y), max(a2.z, a2.w));
                    unsigned t3 = max(max(a3.x, a3.y), max(a3.z, a3.w));
                    unsigned t4 = max(max(a4.x, a4.y), max(a4.z, a4.w));
                    unsigned t5 = max(max(a5.x, a5.y), max(a5.z, a5.w));
                    unsigned t6 = max(max(a6.x, a6.y), max(a6.z, a6.w));
                    unsigned t7 = max(max(a7.x, a7.y), max(a7.z, a7.w));
                    unsigned nv = max(max(max(t0, t1), max(t2, t3)),
                                      max(max(t4, t5), max(t6, t7)));
                    if (myseg < 32) v0 = nv; else v1 = nv;
                }
            }
            __syncwarp();
            int c0 = scand[lane];
            int c1 = (lane + 32 < NCAND) ? scand[lane + 32] : 0x7fffffff;
            int r0 = 0, r1 = 0;
            for (int j = 0; j < NCAND; j++) {
                int cj = scand[j];
                r0 += (cj < c0);
                r1 += (cj < c1);
            }
            scand2[r0] = c0;
            if (lane + 32 < NCAND) scand2[r1] = c1;
        }
        __syncthreads();

        const float* pb = g_prob + (size_t)b * TT * CC;
        for (int e = tid; e < NTR * NCAND; e += 256) {
            int tr_i = e / NCAND;
            int n = e % NCAND;
            int cn = scand2[n];
            int ca = s_tr[tr_i], cb = s_tr[tr_i + 1];
            float sacc = 0.f;
            #pragma unroll
            for (int sft = 0; sft < CSZ; sft++) {
                int r = cn + sft - 7;
                if (r >= 0 && r < TT) {
                    float sign = (sft < 7) ? 1.f : -1.f;
                    sacc += sign * (pb[r * CC + ca] - pb[r * CC + cb]);
                }
            }
            scls[e] = sacc * (1.f / 30.f) + sfs[cn];
        }
        __syncthreads();

        if (tid < 32) {
            int j = lane;
            const float FINF = INFINITY;
            bool active = (j < 31);
            float prev;
            if (j == 0) prev = 0.f;
            else if (j == 1) prev = -scls[0 * NCAND + 0];
            else prev = FINF;
            if (active) sdir[j] = (j == 1) ? 1 : 0;
            int ta = j >> 1; if (ta > NTR - 1) ta = NTR - 1;
            bool even = ((j & 1) == 0);
            for (int ii = 1; ii < NCAND; ii++) {
                float dm1 = __shfl_up_sync(0xffffffffu, prev, 1);
                float dm2 = __shfl_up_sync(0xffffffffu, prev, 2);
                if (j < 1) dm1 = FINF;
                if (j < 2) dm2 = FINF;
                float nv; signed char nd;
                if (j >= 2) {
                    if (even) {
                        nv = fminf(prev, dm1);
                        nd = (prev < dm1) ? 0 : 1;
                    } else {
                        nv = -scls[ta * NCAND + ii] + fminf(dm1, dm2);
                        nd = (dm1 < dm2) ? 1 : 2;
                    }
                } else if (j == 0) {
                    nv = (ii < NCAND - NTR) ? 0.f : FINF; nd = 0;
                } else {
                    bool ok = (ii <= NCAND - NTR);
                    nv = ok ? -scls[0 * NCAND + ii] : FINF;
                    nd = ok ? 1 : 0;
                }
                prev = nv;
                if (active) sdir[ii * 31 + j] = nd;
            }
            float p30 = __shfl_sync(0xffffffffu, prev, 30);
            float p29 = __shfl_sync(0xffffffffu, prev, 29);
            if (j == 0) {
                int cj = (p30 < p29) ? 30 : 29;
                int outi[NCAND];
                #pragma unroll
                for (int ii = NCAND - 1; ii >= 0; ii--) {
                    outi[ii] = (cj & 1) ? (cj >> 1) : NTR;
                    cj -= sdir[ii * 31 + cj];
                }
                int res[NTR];
                #pragma unroll
                for (int k2 = 0; k2 < NTR; k2++) res[k2] = 0;
                #pragma unroll
                for (int ii = 0; ii < NCAND; ii++) {
                    int oi = outi[ii];
                    if (oi < NTR) res[oi] = ii;
                }
                #pragma unroll
                for (int k2 = 0; k2 < NTR; k2++)
                    g_bdy[b * NTR + k2] = scand2[res[k2]];
            }
        }
    }

    // =================== grid barrier (96 blocks) ===========================
    bar45();

    // blocks 0..3 used transcript[blk] in phase 1; phase 2 needs transcript[b5]
    if (blk < BB) {
        __syncthreads();
        if (tid < LL) s_tr[tid] = transcript[b5 * LL + tid];
        __syncthreads();
    }

    // =================== Phase 2: CE + GLC ==================================
    {
        int b = b5;
        if (role < 8) {
            __shared__ int sbdy[NTR];
            if (tid < NTR) sbdy[tid] = g_bdy[b * NTR + tid];
            __syncthreads();
            int t = role * 256 + tid;
            int cnt = 0;
            #pragma unroll
            for (int j = 0; j < NTR; j++) cnt += (t >= sbdy[j]) ? 1 : 0;
            int cid = s_tr[cnt];
            float lce = g_lse[b * TT + t] - fr_logit[(size_t)(b * TT + t) * CC + cid];
            #pragma unroll
            for (int o = 16; o > 0; o >>= 1) lce += __shfl_xor_sync(0xffffffffu, lce, o);
            if (lane == 0) sred[w] = lce;
            __syncthreads();
            if (tid == 0) {
                float s = 0.f;
                #pragma unroll
                for (int ww = 0; ww < 8; ww++) s += sred[ww];
                g_fr32[b * 8 + role] = s;
            }
        } else {
            int k = role - 8;
            __shared__ int sb[NTR];
            __shared__ int s_m;
            __shared__ float4 sla4[DD / 4];
            __shared__ float4 stmp[DD / 4];
            __shared__ float s_sim[CC];
            __shared__ float snrm;
            if (tid < NTR) sb[tid] = g_bdy[b * NTR + tid];
            __syncthreads();
            if (tid < LL) {
                int v = s_tr[tid];
                int rank = 0;
                #pragma unroll
                for (int i = 0; i < LL; i++) rank += (s_tr[i] < v) ? 1 : 0;
                if (rank == k) s_m = tid;
            }
            __syncthreads();
            int m = s_m;
            int label = s_tr[m];
            int lo = (m == 0) ? 0 : sb[m - 1];
            int hi = (m == LL - 1) ? TT : sb[m];
            int cnt = hi - lo;

            int q = tid & 127;
            int half = tid >> 7;
            const float4* fb4 = (const float4*)(feat + ((size_t)b * (CC + TT) + CC) * DD);
            float4 a0 = make_float4(0.f, 0.f, 0.f, 0.f);
            float4 a1 = a0, a2 = a0, a3 = a0;
            int t = lo + half;
            for (; t + 6 < hi; t += 8) {
                float4 x0 = fb4[(size_t)t * 128 + q];
                float4 x1 = fb4[(size_t)(t + 2) * 128 + q];
                float4 x2 = fb4[(size_t)(t + 4) * 128 + q];
                float4 x3 = fb4[(size_t)(t + 6) * 128 + q];
                a0.x += x0.x; a0.y += x0.y; a0.z += x0.z; a0.w += x0.w;
                a1.x += x1.x; a1.y += x1.y; a1.z += x1.z; a1.w += x1.w;
                a2.x += x2.x; a2.y += x2.y; a2.z += x2.z; a2.w += x2.w;
                a3.x += x3.x; a3.y += x3.y; a3.z += x3.z; a3.w += x3.w;
            }
            for (; t < hi; t += 2) {
                float4 x0 = fb4[(size_t)t * 128 + q];
                a0.x += x0.x; a0.y += x0.y; a0.z += x0.z; a0.w += x0.w;
            }
            a0.x += a1.x + a2.x + a3.x;
            a0.y += a1.y + a2.y + a3.y;
            a0.z += a1.z + a2.z + a3.z;
            a0.w += a1.w + a2.w + a3.w;
            if (half == 1) stmp[q] = a0;
            __syncthreads();
            float sq = 0.f;
            float4 mm = make_float4(0.f, 0.f, 0.f, 0.f);
            if (half == 0) {
                float4 o = stmp[q];
                float fc = (cnt > 0) ? (float)cnt : 1.f;
                float inv = 1.f / fc;
                mm.x = (a0.x + o.x) * inv;
                mm.y = (a0.y + o.y) * inv;
                mm.z = (a0.z + o.z) * inv;
                mm.w = (a0.w + o.w) * inv;
                sq = mm.x * mm.x + mm.y * mm.y + mm.z * mm.z + mm.w * mm.w;
            }
            sred[tid] = sq;
            __syncthreads();
            for (int s = 128; s > 0; s >>= 1) {
                if (tid < s) sred[tid] += sred[tid + s];
                __syncthreads();
            }
            if (tid == 0) snrm = 1.f / fmaxf(sqrtf(sred[0]), 1e-12f);
            __syncthreads();
            if (half == 0) {
                float inm = snrm;
                sla4[q] = make_float4(mm.x * inm, mm.y * inm, mm.z * inm, mm.w * inm);
            }
            __syncthreads();

            const float4* tokb4 = (const float4*)(feat + (size_t)b * (CC + TT) * DD);
            #pragma unroll
            for (int jj = 0; jj < 6; jj++) {
                int j = w * 6 + jj;
                const float4* tkr = tokb4 + (size_t)j * 128;
                float dot = 0.f;
                #pragma unroll
                for (int kk = 0; kk < 4; kk++) {
                    int idx = lane + 32 * kk;
                    float4 tv = tkr[idx];
                    float4 lv = sla4[idx];
                    dot += lv.x * tv.x + lv.y * tv.y + lv.z * tv.z + lv.w * tv.w;
                }
                #pragma unroll
                for (int o = 16; o > 0; o >>= 1)
                    dot += __shfl_xor_sync(0xffffffffu, dot, o);
                if (lane == 0)
                    s_sim[j] = dot * g_n2i[b * CC + j];
            }
            __syncthreads();
            if (tid == 0) {
                float mx = -INFINITY;
                for (int j = 0; j < CC; j++) mx = fmaxf(mx, s_sim[j]);
                float se = 0.f;
                for (int j = 0; j < CC; j++) se += __expf(s_sim[j] - mx);
                float lse = mx + __logf(se);
                g_glc_part[b * LL + k] = lse - s_sim[label];
            }
        }
    }

    // ---- last-block final reduction -----------------------------------------
    __syncthreads();
    if (tid == 0) {
        __threadfence();
        int t = atomicAdd(&g_ticket, 1);
        s_last = (t == NB45 - 1) ? 1 : 0;
    }
    __syncthreads();
    if (s_last) {
        float v = 0.f;
        if (tid < BB * CC) {
            float x = tok_logit[tid];
            float yy = y[tid];
            v = -(yy * log_sigmoid_f(x) + (1.f - yy) * log_sigmoid_f(-x));
        }
        sred[tid] = v;
        __syncthreads();
        for (int s = 128; s > 0; s >>= 1) {
            if (tid < s) sred[tid] += sred[tid + s];
            __syncthreads();
        }
        if (tid == 0) {
            float tok = sred[0] / (float)(BB * CC);
            float frs = 0.f;
            for (int i = 0; i < BB * 8; i++) frs += g_fr32[i];
            float fr = frs / (float)(BB * TT);
            float gs = 0.f;
            for (int i = 0; i < BB * LL; i++) gs += g_glc_part[i];
            float glc = gs / (float)(BB * LL);
            out[0] = tok + fr + 0.1f * glc;
            g_ticket = 0;   // reset for next graph replay
        }
    }
}

// ------------------- launch (4-node PDL chain) ------------------------------
static void launch_pdl(const void* func, dim3 grid, dim3 block, void** args) {
    cudaLaunchConfig_t cfg = {};
    cfg.gridDim = grid;
    cfg.blockDim = block;
    cfg.stream = 0;
    cudaLaunchAttribute attr[1];
    attr[0].id = cudaLaunchAttributeProgrammaticStreamSerialization;
    attr[0].val.programmaticStreamSerializationAllowed = 1;
    cfg.attrs = attr;
    cfg.numAttrs = 1;
    cudaLaunchKernelExC(&cfg, func, args);
}

extern "C" void kernel_launch(void* const* d_in, const int* in_sizes, int n_in,
                              void* d_out, int out_size) {
    const float* tok_logit  = (const float*)d_in[1];
    const float* fr_logit   = (const float*)d_in[2];
    const int*   transcript = (const int*)d_in[4];
    const float* vid        = (const float*)d_in[5];
    const float* feat       = (const float*)d_in[6];
    float* out = (float*)d_out;

    k1_softmax<<<(BB * TT) / 8 + BB, 256>>>(fr_logit, feat);
    {
        void* args[] = {};
        launch_pdl((const void*)k2_cross, dim3((BB * 8 * TP8) / 16), dim3(256), args);
    }
    {
        void* args[] = {};
        launch_pdl((const void*)k3_score, dim3((BB * TT + 255) / 256), dim3(256), args);
    }
    {
        void* args[] = {(void*)&fr_logit, (void*)&transcript, (void*)&feat,
                        (void*)&tok_logit, (void*)&vid, (void*)&out};
        launch_pdl((const void*)k45, dim3(NB45), dim3(256), args);
    }
}

// round 15
// speedup vs baseline: 1.0822x; 1.0822x over previous
#include <cuda_runtime.h>
#include <math.h>

#define BB 4
#define TT 2048
#define CC 48
#define DD 512
#define LL 16
#define KK 9
#define CSZ 15
#define NTR 15
#define NCAND 45
#define WINLEN 19
#define TP8 (TT + 8)
#define NB45 96

// ------------------- device scratch (static, no allocs) -------------------
__device__ float g_prob[BB * TT * CC];
__device__ float g_lse[BB * TT];
__device__ float g_ent2[BB * TT];
__device__ float g_cross[BB * 8 * TP8];
__device__ float g_score[BB * TT];
__device__ int   g_bdy[BB * NTR];
__device__ float g_fr32[BB * 8];
__device__ float g_glc_part[BB * LL];
__device__ float g_n2i[BB * CC];
__device__ float4 g_tilesum[BB * 16 * 128];   // per-batch 128-row tile sums of fr_feat
__device__ int   g_ticket;
__device__ int   g_cnt45;
__device__ int   g_gen45;

// 96-block spin barrier (all blocks resident by construction)
__device__ __forceinline__ void bar45() {
    __syncthreads();
    if (threadIdx.x == 0) {
        __threadfence();
        int gen = *((volatile int*)&g_gen45);
        if (atomicAdd(&g_cnt45, 1) == NB45 - 1) {
            g_cnt45 = 0;
            __threadfence();
            atomicExch(&g_gen45, gen + 1);
        } else {
            while (*((volatile int*)&g_gen45) == gen) __nanosleep(64);
        }
        __threadfence();
    }
    __syncthreads();
}

__device__ __forceinline__ unsigned f2sortable(float f) {
    unsigned u = __float_as_uint(f);
    return (u & 0x80000000u) ? ~u : (u | 0x80000000u);
}

__device__ __forceinline__ unsigned long long pk2f(float c) {
    unsigned long long r;
    asm("mov.b64 %0, {%1,%1};" : "=l"(r) : "f"(c));
    return r;
}

// Cephes log2 on two values via packed f32x2 FMA pipe
__device__ __forceinline__ float2 fast_log2_x2(float x0, float x1) {
    unsigned u0 = __float_as_uint(x0), u1 = __float_as_uint(x1);
    int e0 = (int)(u0 >> 23) - 127, e1 = (int)(u1 >> 23) - 127;
    float m0 = __uint_as_float((u0 & 0x007fffffu) | 0x3f800000u);
    float m1 = __uint_as_float((u1 & 0x007fffffu) | 0x3f800000u);
    if (m0 > 1.4142135f) { m0 *= 0.5f; e0 += 1; }
    if (m1 > 1.4142135f) { m1 *= 0.5f; e1 += 1; }
    float z0 = m0 - 1.f, z1 = m1 - 1.f;
    unsigned long long Z, Z2, P, W, Y, E, R;
    asm("mov.b64 %0, {%1,%2};" : "=l"(Z) : "f"(z0), "f"(z1));
    asm("mul.rn.f32x2 %0, %1, %1;" : "=l"(Z2) : "l"(Z));
    P = pk2f(7.0376836292e-2f);
    asm("fma.rn.f32x2 %0, %1, %2, %3;" : "=l"(P) : "l"(P), "l"(Z), "l"(pk2f(-1.1514610310e-1f)));
    asm("fma.rn.f32x2 %0, %1, %2, %3;" : "=l"(P) : "l"(P), "l"(Z), "l"(pk2f( 1.1676998740e-1f)));
    asm("fma.rn.f32x2 %0, %1, %2, %3;" : "=l"(P) : "l"(P), "l"(Z), "l"(pk2f(-1.2420140846e-1f)));
    asm("fma.rn.f32x2 %0, %1, %2, %3;" : "=l"(P) : "l"(P), "l"(Z), "l"(pk2f( 1.4249322787e-1f)));
    asm("fma.rn.f32x2 %0, %1, %2, %3;" : "=l"(P) : "l"(P), "l"(Z), "l"(pk2f(-1.6668057665e-1f)));
    asm("fma.rn.f32x2 %0, %1, %2, %3;" : "=l"(P) : "l"(P), "l"(Z), "l"(pk2f( 2.0000714765e-1f)));
    asm("fma.rn.f32x2 %0, %1, %2, %3;" : "=l"(P) : "l"(P), "l"(Z), "l"(pk2f(-2.4999993993e-1f)));
    asm("fma.rn.f32x2 %0, %1, %2, %3;" : "=l"(P) : "l"(P), "l"(Z), "l"(pk2f( 3.3333331174e-1f)));
    asm("fma.rn.f32x2 %0, %1, %2, %3;" : "=l"(W) : "l"(Z2), "l"(pk2f(-0.5f)), "l"(Z));
    asm("mul.rn.f32x2 %0, %1, %2;" : "=l"(P) : "l"(P), "l"(Z));
    asm("fma.rn.f32x2 %0, %1, %2, %3;" : "=l"(Y) : "l"(P), "l"(Z2), "l"(W));
    float ef0 = (float)e0, ef1 = (float)e1;
    asm("mov.b64 %0, {%1,%2};" : "=l"(E) : "f"(ef0), "f"(ef1));
    asm("fma.rn.f32x2 %0, %1, %2, %3;" : "=l"(R) : "l"(Y), "l"(pk2f(1.44269504089f)), "l"(E));
    float r0, r1;
    asm("mov.b64 {%0,%1}, %2;" : "=f"(r0), "=f"(r1) : "l"(R));
    return make_float2(r0, r1);
}

__device__ __forceinline__ float log_sigmoid_f(float x) {
    return (x >= 0.f) ? -log1pf(__expf(-x)) : x - log1pf(__expf(x));
}

// ------------------- K1: softmax rows + lse + ent2, plus token norms -------
__global__ void k1_softmax(const float* __restrict__ fr,
                           const float* __restrict__ feat) {
    if (blockIdx.x >= (BB * TT) / 8) {
        int b = blockIdx.x - (BB * TT) / 8;
        int w = threadIdx.x >> 5;
        int lane = threadIdx.x & 31;
        const float4* tokb4 = (const float4*)(feat + (size_t)b * (CC + TT) * DD);
        #pragma unroll
        for (int jj = 0; jj < 6; jj++) {
            int j = w * 6 + jj;
            const float4* tkr = tokb4 + (size_t)j * 128;
            float n2 = 0.f;
            #pragma unroll
            for (int kk = 0; kk < 4; kk++) {
                float4 tv = tkr[lane + 32 * kk];
                n2 += tv.x * tv.x + tv.y * tv.y + tv.z * tv.z + tv.w * tv.w;
            }
            #pragma unroll
            for (int o = 16; o > 0; o >>= 1) n2 += __shfl_xor_sync(0xffffffffu, n2, o);
            if (lane == 0) g_n2i[b * CC + j] = 10.f / fmaxf(sqrtf(n2), 1e-12f);
        }
        return;
    }
    int gw = (blockIdx.x * blockDim.x + threadIdx.x) >> 5;
    int lane = threadIdx.x & 31;
    const float* row = fr + (size_t)gw * CC;
    float x0 = row[lane];
    float x1 = (lane < 16) ? row[lane + 32] : -INFINITY;
    float m = fmaxf(x0, x1);
    #pragma unroll
    for (int o = 16; o > 0; o >>= 1) m = fmaxf(m, __shfl_xor_sync(0xffffffffu, m, o));
    float e0 = __expf(x0 - m);
    float e1 = (lane < 16) ? __expf(x1 - m) : 0.f;
    float s = e0 + e1;
    #pragma unroll
    for (int o = 16; o > 0; o >>= 1) s += __shfl_xor_sync(0xffffffffu, s, o);
    float inv = 1.f / s;
    float p0 = e0 * inv, p1 = e1 * inv;
    float ent = (p0 > 0.f) ? p0 * __log2f(p0) : 0.f;
    if (lane < 16) ent += (p1 > 0.f) ? p1 * __log2f(p1) : 0.f;
    #pragma unroll
    for (int o = 16; o > 0; o >>= 1) ent += __shfl_xor_sync(0xffffffffu, ent, o);
    float* pr = g_prob + (size_t)gw * CC;
    pr[lane] = p0;
    if (lane < 16) pr[lane + 32] = p1;
    if (lane == 0) {
        g_lse[gw] = m + __logf(s);
        g_ent2[gw] = ent;
    }
}

// ------------------- K2: crossD, 2 tasks per warp, float4, 3:5 split -------
__global__ void k2_cross() {
    int gw = (blockIdx.x * blockDim.x + threadIdx.x) >> 5;
    int lane = threadIdx.x & 31;
    int group = lane >> 4;
    int gl = lane & 15;
    cudaGridDependencySynchronize();

    int task = gw * 2 + group;
    int b = task / (8 * TP8);
    int rem = task % (8 * TP8);
    int d = rem / TP8 + 1;
    int r4 = rem % TP8;
    int r1 = r4 - 4;
    int r2 = r1 + d;

    const float4* base = (const float4*)(g_prob + (size_t)b * TT * CC);
    float acc = 0.f;
    if (gl < 12) {
        float4 a = (r1 >= 0 && r1 < TT) ? base[r1 * 12 + gl]
                                        : make_float4(0.f, 0.f, 0.f, 0.f);
        float4 c = (r2 >= 0 && r2 < TT) ? base[r2 * 12 + gl]
                                        : make_float4(0.f, 0.f, 0.f, 0.f);
        float sv0 = a.x + c.x, sv1 = a.y + c.y;
        float sv2 = a.z + c.z, sv3 = a.w + c.w;
        float xx0 = 0.5f * sv0 + 1e-32f;
        float xx1 = 0.5f * sv1 + 1e-32f;
        float xx2 = 0.5f * sv2 + 1e-32f;
        float xx3 = 0.5f * sv3 + 1e-32f;
        float lg0, lg1, lg2, lg3;
        if (d <= 3) {
            float2 la = fast_log2_x2(xx0, xx1);
            float2 lb = fast_log2_x2(xx2, xx3);
            lg0 = la.x; lg1 = la.y; lg2 = lb.x; lg3 = lb.y;
        } else {
            lg0 = __log2f(xx0);
            lg1 = __log2f(xx1);
            lg2 = __log2f(xx2);
            lg3 = __log2f(xx3);
        }
        acc = sv0 * lg0 + sv1 * lg1 + sv2 * lg2 + sv3 * lg3;
    }
    #pragma unroll
    for (int o = 8; o > 0; o >>= 1) acc += __shfl_xor_sync(0xffffffffu, acc, o);
    if (gl == 0) g_cross[(b * 8 + (d - 1)) * TP8 + r4] = acc;
}

// ------------------- K3: boundary score per (b,t) --------------------------
__global__ void k3_score() {
    int idx = blockIdx.x * blockDim.x + threadIdx.x;
    cudaGridDependencySynchronize();
    if (idx >= BB * TT) return;
    int b = idx / TT;
    int t = idx % TT;
    float se = 0.f;
    #pragma unroll
    for (int i = 0; i < 4; i++) {
        int r = t - 4 + i;
        se += (r >= 0) ? g_ent2[b * TT + r] : 0.f;
    }
    float cs = 0.f;
    #pragma unroll
    for (int d = 1; d <= 8; d++) {
        const float* crb = g_cross + (size_t)(b * 8 + d - 1) * TP8 + t;
        #pragma unroll
        for (int i = 0; i + d <= 8; i++) {
            float w = ((i < 4) == ((i + d) < 4)) ? 2.f : -2.f;
            cs += w * crb[i];
        }
    }
    float sc = (4.f * se + cs) * (1.f / 81.f);
    if (t == 0) sc = -INFINITY;
    g_score[idx] = sc;
}

// ------------------- K45: detect + tilesum (shadow) + barrier + CE/GLC -----
__global__ void k45(const float* __restrict__ fr_logit,
                    const int* __restrict__ transcript,
                    const float* __restrict__ feat,
                    const float* __restrict__ tok_logit,
                    const float* __restrict__ y,
                    float* __restrict__ out) {
    __shared__ __align__(16) unsigned ss[TT];
    __shared__ float sfs[TT];
    __shared__ int scand[NCAND];
    __shared__ int scand2[NCAND];
    __shared__ float scls[NTR * NCAND];
    __shared__ signed char sdir[NCAND * 31];
    __shared__ int s_tr[LL];
    __shared__ float sred[256];
    __shared__ int s_last;
    __shared__ float4 sla4[DD / 4];
    __shared__ float4 stmp[DD / 4];
    __shared__ float s_sim[CC];
    __shared__ int sb[NTR];
    __shared__ int s_m;
    __shared__ float snrm;

    int blk = blockIdx.x;
    int tid = threadIdx.x;
    int lane = tid & 31;
    int w = tid >> 5;

    int b5 = blk / 24;
    int role = blk % 24;
    int btr = (blk < BB) ? blk : b5;
    if (tid < LL) s_tr[tid] = transcript[btr * LL + tid];
    cudaGridDependencySynchronize();       // PDL: wait for k3's g_score

    // =================== Phase 1 ===========================================
    if (blk < BB) {
        // ---- detect: argmax + sort + cls + DP (unchanged) ------------------
        int b = blk;
        for (int t = tid; t < TT; t += 256) {
            float sc = g_score[b * TT + t];
            sfs[t] = sc;
            ss[t] = f2sortable(sc);
        }
        __syncthreads();

        if (tid < 32) {
            const uint4* ss4 = (const uint4*)ss;
            unsigned v0 = 0u, v1 = 0u;
            #pragma unroll
            for (int q = 0; q < 8; q++) {
                uint4 a = ss4[lane * 8 + q];
                uint4 c = ss4[(lane + 32) * 8 + q];
                v0 = max(v0, max(max(a.x, a.y), max(a.z, a.w)));
                v1 = max(v1, max(max(c.x, c.y), max(c.z, c.w)));
            }
            for (int it = 0; it < NCAND; it++) {
                unsigned loc = max(v0, v1);
                unsigned mv = __reduce_max_sync(0xffffffffu, loc);
                unsigned m0 = __ballot_sync(0xffffffffu, v0 == mv);
                unsigned m1 = __ballot_sync(0xffffffffu, v1 == mv);
                int seg = m0 ? (__ffs(m0) - 1) : (32 + __ffs(m1) - 1);
                unsigned val = ss[seg * 32 + lane];
                unsigned mk = __ballot_sync(0xffffffffu, val == mv);
                int pick = seg * 32 + (__ffs(mk) - 1);
                if (lane == 0) scand[it] = pick;

                int lo = pick - WINLEN, hi = pick + WINLEN;
                int p0 = lo + lane;
                if (p0 >= 0 && p0 < TT) ss[p0] = 0u;
                int p1 = p0 + 32;
                if (p1 <= hi && p1 < TT) ss[p1] = 0u;
                __syncwarp();

                int slo = (lo < 0 ? 0 : lo) >> 5;
                int shi = ((hi > TT - 1 ? TT - 1 : hi)) >> 5;
                int myseg = (lane >= slo && lane <= shi) ? lane
                          : ((lane + 32 >= slo && lane + 32 <= shi) ? lane + 32 : -1);
                if (myseg >= 0) {
                    const uint4* sp = (const uint4*)(ss + myseg * 32);
                    uint4 a0 = sp[0], a1 = sp[1], a2 = sp[2], a3 = sp[3];
                    uint4 a4 = sp[4], a5 = sp[5], a6 = sp[6], a7 = sp[7];
                    unsigned t0 = max(max(a0.x, a0.y), max(a0.z, a0.w));
                    unsigned t1 = max(max(a1.x, a1.y), max(a1.z, a1.w));
                    unsigned t2 = max(max(a2.x, a2.y), max(a2.z, a2.w));
                    unsigned t3 = max(max(a3.x, a3.y), max(a3.z, a3.w));
                    unsigned t4 = max(max(a4.x, a4.y), max(a4.z, a4.w));
                    unsigned t5 = max(max(a5.x, a5.y), max(a5.z, a5.w));
                    unsigned t6 = max(max(a6.x, a6.y), max(a6.z, a6.w));
                    unsigned t7 = max(max(a7.x, a7.y), max(a7.z, a7.w));
                    unsigned nv = max(max(max(t0, t1), max(t2, t3)),
                                      max(max(t4, t5), max(t6, t7)));
                    if (myseg < 32) v0 = nv; else v1 = nv;
                }
            }
            __syncwarp();
            int c0 = scand[lane];
            int c1 = (lane + 32 < NCAND) ? scand[lane + 32] : 0x7fffffff;
            int r0 = 0, r1 = 0;
            for (int j = 0; j < NCAND; j++) {
                int cj = scand[j];
                r0 += (cj < c0);
                r1 += (cj < c1);
            }
            scand2[r0] = c0;
            if (lane + 32 < NCAND) scand2[r1] = c1;
        }
        __syncthreads();

        const float* pb = g_prob + (size_t)b * TT * CC;
        for (int e = tid; e < NTR * NCAND; e += 256) {
            int tr_i = e / NCAND;
            int n = e % NCAND;
            int cn = scand2[n];
            int ca = s_tr[tr_i], cb = s_tr[tr_i + 1];
            float sacc = 0.f;
            #pragma unroll
            for (int sft = 0; sft < CSZ; sft++) {
                int r = cn + sft - 7;
                if (r >= 0 && r < TT) {
                    float sign = (sft < 7) ? 1.f : -1.f;
                    sacc += sign * (pb[r * CC + ca] - pb[r * CC + cb]);
                }
            }
            scls[e] = sacc * (1.f / 30.f) + sfs[cn];
        }
        __syncthreads();

        if (tid < 32) {
            int j = lane;
            const float FINF = INFINITY;
            bool active = (j < 31);
            float prev;
            if (j == 0) prev = 0.f;
            else if (j == 1) prev = -scls[0 * NCAND + 0];
            else prev = FINF;
            if (active) sdir[j] = (j == 1) ? 1 : 0;
            int ta = j >> 1; if (ta > NTR - 1) ta = NTR - 1;
            bool even = ((j & 1) == 0);
            for (int ii = 1; ii < NCAND; ii++) {
                float dm1 = __shfl_up_sync(0xffffffffu, prev, 1);
                float dm2 = __shfl_up_sync(0xffffffffu, prev, 2);
                if (j < 1) dm1 = FINF;
                if (j < 2) dm2 = FINF;
                float nv; signed char nd;
                if (j >= 2) {
                    if (even) {
                        nv = fminf(prev, dm1);
                        nd = (prev < dm1) ? 0 : 1;
                    } else {
                        nv = -scls[ta * NCAND + ii] + fminf(dm1, dm2);
                        nd = (dm1 < dm2) ? 1 : 2;
                    }
                } else if (j == 0) {
                    nv = (ii < NCAND - NTR) ? 0.f : FINF; nd = 0;
                } else {
                    bool ok = (ii <= NCAND - NTR);
                    nv = ok ? -scls[0 * NCAND + ii] : FINF;
                    nd = ok ? 1 : 0;
                }
                prev = nv;
                if (active) sdir[ii * 31 + j] = nd;
            }
            float p30 = __shfl_sync(0xffffffffu, prev, 30);
            float p29 = __shfl_sync(0xffffffffu, prev, 29);
            if (j == 0) {
                int cj = (p30 < p29) ? 30 : 29;
                int outi[NCAND];
                #pragma unroll
                for (int ii = NCAND - 1; ii >= 0; ii--) {
                    outi[ii] = (cj & 1) ? (cj >> 1) : NTR;
                    cj -= sdir[ii * 31 + cj];
                }
                int res[NTR];
                #pragma unroll
                for (int k2 = 0; k2 < NTR; k2++) res[k2] = 0;
                #pragma unroll
                for (int ii = 0; ii < NCAND; ii++) {
                    int oi = outi[ii];
                    if (oi < NTR) res[oi] = ii;
                }
                #pragma unroll
                for (int k2 = 0; k2 < NTR; k2++)
                    g_bdy[b * NTR + k2] = scand2[res[k2]];
            }
        }
    } else if (blk < BB + 64) {
        // ---- tile sums of fr_feat in the argmax shadow ---------------------
        int bt = blk - BB;
        int b = bt >> 4, tile = bt & 15;
        int q = tid & 127;
        int half = tid >> 7;
        const float4* fb4 = (const float4*)(feat + ((size_t)b * (CC + TT) + CC) * DD);
        int rb = tile * 128;
        float4 a0 = make_float4(0.f, 0.f, 0.f, 0.f);
        float4 a1 = a0, a2 = a0, a3 = a0;
        #pragma unroll 4
        for (int r = 0; r < 128; r += 8) {
            float4 x0 = fb4[(size_t)(rb + r + half) * 128 + q];
            float4 x1 = fb4[(size_t)(rb + r + 2 + half) * 128 + q];
            float4 x2 = fb4[(size_t)(rb + r + 4 + half) * 128 + q];
            float4 x3 = fb4[(size_t)(rb + r + 6 + half) * 128 + q];
            a0.x += x0.x; a0.y += x0.y; a0.z += x0.z; a0.w += x0.w;
            a1.x += x1.x; a1.y += x1.y; a1.z += x1.z; a1.w += x1.w;
            a2.x += x2.x; a2.y += x2.y; a2.z += x2.z; a2.w += x2.w;
            a3.x += x3.x; a3.y += x3.y; a3.z += x3.z; a3.w += x3.w;
        }
        a0.x += a1.x + a2.x + a3.x;
        a0.y += a1.y + a2.y + a3.y;
        a0.z += a1.z + a2.z + a3.z;
        a0.w += a1.w + a2.w + a3.w;
        if (half == 1) stmp[q] = a0;
        __syncthreads();
        if (half == 0) {
            float4 o = stmp[q];
            g_tilesum[(b * 16 + tile) * 128 + q] =
                make_float4(a0.x + o.x, a0.y + o.y, a0.z + o.z, a0.w + o.w);
        }
    }

    // =================== grid barrier (96 blocks) ===========================
    bar45();

    if (blk < BB) {
        __syncthreads();
        if (tid < LL) s_tr[tid] = transcript[b5 * LL + tid];
        __syncthreads();
    }

    // =================== Phase 2: CE + GLC ==================================
    {
        int b = b5;
        if (role < 8) {
            if (tid < NTR) sb[tid] = g_bdy[b * NTR + tid];
            __syncthreads();
            int t = role * 256 + tid;
            int cnt = 0;
            #pragma unroll
            for (int j = 0; j < NTR; j++) cnt += (t >= sb[j]) ? 1 : 0;
            int cid = s_tr[cnt];
            float lce = g_lse[b * TT + t] - fr_logit[(size_t)(b * TT + t) * CC + cid];
            #pragma unroll
            for (int o = 16; o > 0; o >>= 1) lce += __shfl_xor_sync(0xffffffffu, lce, o);
            if (lane == 0) sred[w] = lce;
            __syncthreads();
            if (tid == 0) {
                float s = 0.f;
                #pragma unroll
                for (int ww = 0; ww < 8; ww++) s += sred[ww];
                g_fr32[b * 8 + role] = s;
            }
        } else {
            int k = role - 8;
            if (tid < NTR) sb[tid] = g_bdy[b * NTR + tid];
            __syncthreads();
            if (tid < LL) {
                int v = s_tr[tid];
                int rank = 0;
                #pragma unroll
                for (int i = 0; i < LL; i++) rank += (s_tr[i] < v) ? 1 : 0;
                if (rank == k) s_m = tid;
            }
            __syncthreads();
            int m = s_m;
            int label = s_tr[m];
            int lo = (m == 0) ? 0 : sb[m - 1];
            int hi = (m == LL - 1) ? TT : sb[m];
            int cnt = hi - lo;

            int q = tid & 127;
            int half = tid >> 7;
            const float4* fb4 = (const float4*)(feat + ((size_t)b * (CC + TT) + CC) * DD);
            const float4* ts = g_tilesum + (size_t)(b * 16) * 128;
            float4 a0 = make_float4(0.f, 0.f, 0.f, 0.f);
            float4 a1 = a0, a2 = a0;
            int tlo = (lo + 127) >> 7;    // first full tile
            int thi = hi >> 7;            // one past last full tile
            if (tlo <= thi) {
                for (int t2 = tlo + half; t2 < thi; t2 += 2) {
                    float4 x = ts[t2 * 128 + q];
                    a0.x += x.x; a0.y += x.y; a0.z += x.z; a0.w += x.w;
                }
                for (int r = lo + half, e = tlo << 7; r < e; r += 2) {
                    float4 x = fb4[(size_t)r * 128 + q];
                    a1.x += x.x; a1.y += x.y; a1.z += x.z; a1.w += x.w;
                }
                for (int r = (thi << 7) + half; r < hi; r += 2) {
                    float4 x = fb4[(size_t)r * 128 + q];
                    a2.x += x.x; a2.y += x.y; a2.z += x.z; a2.w += x.w;
                }
            } else {
                for (int r = lo + half; r < hi; r += 2) {
                    float4 x = fb4[(size_t)r * 128 + q];
                    a0.x += x.x; a0.y += x.y; a0.z += x.z; a0.w += x.w;
                }
            }
            a0.x += a1.x + a2.x;
            a0.y += a1.y + a2.y;
            a0.z += a1.z + a2.z;
            a0.w += a1.w + a2.w;
            if (half == 1) stmp[q] = a0;
            __syncthreads();
            float sq = 0.f;
            float4 mm = make_float4(0.f, 0.f, 0.f, 0.f);
            if (half == 0) {
                float4 o = stmp[q];
                float fc = (cnt > 0) ? (float)cnt : 1.f;
                float inv = 1.f / fc;
                mm.x = (a0.x + o.x) * inv;
                mm.y = (a0.y + o.y) * inv;
                mm.z = (a0.z + o.z) * inv;
                mm.w = (a0.w + o.w) * inv;
                sq = mm.x * mm.x + mm.y * mm.y + mm.z * mm.z + mm.w * mm.w;
            }
            sred[tid] = sq;
            __syncthreads();
            for (int s = 128; s > 0; s >>= 1) {
                if (tid < s) sred[tid] += sred[tid + s];
                __syncthreads();
            }
            if (tid == 0) snrm = 1.f / fmaxf(sqrtf(sred[0]), 1e-12f);
            __syncthreads();
            if (half == 0) {
                float inm = snrm;
                sla4[q] = make_float4(mm.x * inm, mm.y * inm, mm.z * inm, mm.w * inm);
            }
            __syncthreads();

            const float4* tokb4 = (const float4*)(feat + (size_t)b * (CC + TT) * DD);
            #pragma unroll
            for (int jj = 0; jj < 6; jj++) {
                int j = w * 6 + jj;
                const float4* tkr = tokb4 + (size_t)j * 128;
                float dot = 0.f;
                #pragma unroll
                for (int kk = 0; kk < 4; kk++) {
                    int idx = lane + 32 * kk;
                    float4 tv = tkr[idx];
                    float4 lv = sla4[idx];
                    dot += lv.x * tv.x + lv.y * tv.y + lv.z * tv.z + lv.w * tv.w;
                }
                #pragma unroll
                for (int o = 16; o > 0; o >>= 1)
                    dot += __shfl_xor_sync(0xffffffffu, dot, o);
                if (lane == 0)
                    s_sim[j] = dot * g_n2i[b * CC + j];
            }
            __syncthreads();
            if (tid == 0) {
                float mx = -INFINITY;
                for (int j = 0; j < CC; j++) mx = fmaxf(mx, s_sim[j]);
                float se = 0.f;
                for (int j = 0; j < CC; j++) se += __expf(s_sim[j] - mx);
                float lse = mx + __logf(se);
                g_glc_part[b * LL + k] = lse - s_sim[label];
            }
        }
    }

    // ---- last-block final reduction -----------------------------------------
    __syncthreads();
    if (tid == 0) {
        __threadfence();
        int t = atomicAdd(&g_ticket, 1);
        s_last = (t == NB45 - 1) ? 1 : 0;
    }
    __syncthreads();
    if (s_last) {
        float v = 0.f;
        if (tid < BB * CC) {
            float x = tok_logit[tid];
            float yy = y[tid];
            v = -(yy * log_sigmoid_f(x) + (1.f - yy) * log_sigmoid_f(-x));
        }
        sred[tid] = v;
        __syncthreads();
        for (int s = 128; s > 0; s >>= 1) {
            if (tid < s) sred[tid] += sred[tid + s];
            __syncthreads();
        }
        if (tid == 0) {
            float tok = sred[0] / (float)(BB * CC);
            float frs = 0.f;
            for (int i = 0; i < BB * 8; i++) frs += g_fr32[i];
            float fr = frs / (float)(BB * TT);
            float gs = 0.f;
            for (int i = 0; i < BB * LL; i++) gs += g_glc_part[i];
            float glc = gs / (float)(BB * LL);
            out[0] = tok + fr + 0.1f * glc;
            g_ticket = 0;
        }
    }
}

// ------------------- launch (4-node PDL chain) ------------------------------
static void launch_pdl(const void* func, dim3 grid, dim3 block, void** args) {
    cudaLaunchConfig_t cfg = {};
    cfg.gridDim = grid;
    cfg.blockDim = block;
    cfg.stream = 0;
    cudaLaunchAttribute attr[1];
    attr[0].id = cudaLaunchAttributeProgrammaticStreamSerialization;
    attr[0].val.programmaticStreamSerializationAllowed = 1;
    cfg.attrs = attr;
    cfg.numAttrs = 1;
    cudaLaunchKernelExC(&cfg, func, args);
}

extern "C" void kernel_launch(void* const* d_in, const int* in_sizes, int n_in,
                              void* d_out, int out_size) {
    const float* tok_logit  = (const float*)d_in[1];
    const float* fr_logit   = (const float*)d_in[2];
    const int*   transcript = (const int*)d_in[4];
    const float* vid        = (const float*)d_in[5];
    const float* feat       = (const float*)d_in[6];
    float* out = (float*)d_out;

    k1_softmax<<<(BB * TT) / 8 + BB, 256>>>(fr_logit, feat);
    {
        void* args[] = {};
        launch_pdl((const void*)k2_cross, dim3((BB * 8 * TP8) / 16), dim3(256), args);
    }
    {
        void* args[] = {};
        launch_pdl((const void*)k3_score, dim3((BB * TT + 255) / 256), dim3(256), args);
    }
    {
        void* args[] = {(void*)&fr_logit, (void*)&transcript, (void*)&feat,
                        (void*)&tok_logit, (void*)&vid, (void*)&out};
        launch_pdl((const void*)k45, dim3(NB45), dim3(256), args);
    }
}

// round 16
// speedup vs baseline: 1.1102x; 1.0258x over previous
#include <cuda_runtime.h>
#include <math.h>

#define BB 4
#define TT 2048
#define CC 48
#define DD 512
#define LL 16
#define KK 9
#define CSZ 15
#define NTR 15
#define NCAND 45
#define WINLEN 19
#define TP8 (TT + 8)
#define NB45 96

// ------------------- device scratch (static, no allocs) -------------------
__device__ float g_prob[BB * TT * CC];
__device__ float g_lse[BB * TT];
__device__ float g_ent2[BB * TT];
__device__ float g_cross[BB * 8 * TP8];
__device__ float g_score[BB * TT];
__device__ int   g_bdy[BB * NTR];
__device__ float g_fr32[BB * 8];
__device__ float g_glc_part[BB * LL];
__device__ float g_n2i[BB * CC];
__device__ float4 g_tilesum[BB * 16 * 128];
__device__ int   g_prod[BB];              // per-batch score-producer counters
__device__ int   g_ticket;
__device__ int   g_cnt45;
__device__ int   g_gen45;

// 96-block spin barrier (all blocks resident by construction)
__device__ __forceinline__ void bar45() {
    __syncthreads();
    if (threadIdx.x == 0) {
        __threadfence();
        int gen = *((volatile int*)&g_gen45);
        if (atomicAdd(&g_cnt45, 1) == NB45 - 1) {
            g_cnt45 = 0;
            __threadfence();
            atomicExch(&g_gen45, gen + 1);
        } else {
            while (*((volatile int*)&g_gen45) == gen) __nanosleep(64);
        }
        __threadfence();
    }
    __syncthreads();
}

__device__ __forceinline__ unsigned f2sortable(float f) {
    unsigned u = __float_as_uint(f);
    return (u & 0x80000000u) ? ~u : (u | 0x80000000u);
}

__device__ __forceinline__ unsigned long long pk2f(float c) {
    unsigned long long r;
    asm("mov.b64 %0, {%1,%1};" : "=l"(r) : "f"(c));
    return r;
}

// Cephes log2 on two values via packed f32x2 FMA pipe
__device__ __forceinline__ float2 fast_log2_x2(float x0, float x1) {
    unsigned u0 = __float_as_uint(x0), u1 = __float_as_uint(x1);
    int e0 = (int)(u0 >> 23) - 127, e1 = (int)(u1 >> 23) - 127;
    float m0 = __uint_as_float((u0 & 0x007fffffu) | 0x3f800000u);
    float m1 = __uint_as_float((u1 & 0x007fffffu) | 0x3f800000u);
    if (m0 > 1.4142135f) { m0 *= 0.5f; e0 += 1; }
    if (m1 > 1.4142135f) { m1 *= 0.5f; e1 += 1; }
    float z0 = m0 - 1.f, z1 = m1 - 1.f;
    unsigned long long Z, Z2, P, W, Y, E, R;
    asm("mov.b64 %0, {%1,%2};" : "=l"(Z) : "f"(z0), "f"(z1));
    asm("mul.rn.f32x2 %0, %1, %1;" : "=l"(Z2) : "l"(Z));
    P = pk2f(7.0376836292e-2f);
    asm("fma.rn.f32x2 %0, %1, %2, %3;" : "=l"(P) : "l"(P), "l"(Z), "l"(pk2f(-1.1514610310e-1f)));
    asm("fma.rn.f32x2 %0, %1, %2, %3;" : "=l"(P) : "l"(P), "l"(Z), "l"(pk2f( 1.1676998740e-1f)));
    asm("fma.rn.f32x2 %0, %1, %2, %3;" : "=l"(P) : "l"(P), "l"(Z), "l"(pk2f(-1.2420140846e-1f)));
    asm("fma.rn.f32x2 %0, %1, %2, %3;" : "=l"(P) : "l"(P), "l"(Z), "l"(pk2f( 1.4249322787e-1f)));
    asm("fma.rn.f32x2 %0, %1, %2, %3;" : "=l"(P) : "l"(P), "l"(Z), "l"(pk2f(-1.6668057665e-1f)));
    asm("fma.rn.f32x2 %0, %1, %2, %3;" : "=l"(P) : "l"(P), "l"(Z), "l"(pk2f( 2.0000714765e-1f)));
    asm("fma.rn.f32x2 %0, %1, %2, %3;" : "=l"(P) : "l"(P), "l"(Z), "l"(pk2f(-2.4999993993e-1f)));
    asm("fma.rn.f32x2 %0, %1, %2, %3;" : "=l"(P) : "l"(P), "l"(Z), "l"(pk2f( 3.3333331174e-1f)));
    asm("fma.rn.f32x2 %0, %1, %2, %3;" : "=l"(W) : "l"(Z2), "l"(pk2f(-0.5f)), "l"(Z));
    asm("mul.rn.f32x2 %0, %1, %2;" : "=l"(P) : "l"(P), "l"(Z));
    asm("fma.rn.f32x2 %0, %1, %2, %3;" : "=l"(Y) : "l"(P), "l"(Z2), "l"(W));
    float ef0 = (float)e0, ef1 = (float)e1;
    asm("mov.b64 %0, {%1,%2};" : "=l"(E) : "f"(ef0), "f"(ef1));
    asm("fma.rn.f32x2 %0, %1, %2, %3;" : "=l"(R) : "l"(Y), "l"(pk2f(1.44269504089f)), "l"(E));
    float r0, r1;
    asm("mov.b64 {%0,%1}, %2;" : "=f"(r0), "=f"(r1) : "l"(R));
    return make_float2(r0, r1);
}

__device__ __forceinline__ float log_sigmoid_f(float x) {
    return (x >= 0.f) ? -log1pf(__expf(-x)) : x - log1pf(__expf(x));
}

// ------------------- K1: softmax rows + lse + ent2, plus token norms -------
__global__ void k1_softmax(const float* __restrict__ fr,
                           const float* __restrict__ feat) {
    if (blockIdx.x >= (BB * TT) / 8) {
        int b = blockIdx.x - (BB * TT) / 8;
        int w = threadIdx.x >> 5;
        int lane = threadIdx.x & 31;
        const float4* tokb4 = (const float4*)(feat + (size_t)b * (CC + TT) * DD);
        #pragma unroll
        for (int jj = 0; jj < 6; jj++) {
            int j = w * 6 + jj;
            const float4* tkr = tokb4 + (size_t)j * 128;
            float n2 = 0.f;
            #pragma unroll
            for (int kk = 0; kk < 4; kk++) {
                float4 tv = tkr[lane + 32 * kk];
                n2 += tv.x * tv.x + tv.y * tv.y + tv.z * tv.z + tv.w * tv.w;
            }
            #pragma unroll
            for (int o = 16; o > 0; o >>= 1) n2 += __shfl_xor_sync(0xffffffffu, n2, o);
            if (lane == 0) g_n2i[b * CC + j] = 10.f / fmaxf(sqrtf(n2), 1e-12f);
        }
        return;
    }
    int gw = (blockIdx.x * blockDim.x + threadIdx.x) >> 5;
    int lane = threadIdx.x & 31;
    const float* row = fr + (size_t)gw * CC;
    float x0 = row[lane];
    float x1 = (lane < 16) ? row[lane + 32] : -INFINITY;
    float m = fmaxf(x0, x1);
    #pragma unroll
    for (int o = 16; o > 0; o >>= 1) m = fmaxf(m, __shfl_xor_sync(0xffffffffu, m, o));
    float e0 = __expf(x0 - m);
    float e1 = (lane < 16) ? __expf(x1 - m) : 0.f;
    float s = e0 + e1;
    #pragma unroll
    for (int o = 16; o > 0; o >>= 1) s += __shfl_xor_sync(0xffffffffu, s, o);
    float inv = 1.f / s;
    float p0 = e0 * inv, p1 = e1 * inv;
    float ent = (p0 > 0.f) ? p0 * __log2f(p0) : 0.f;
    if (lane < 16) ent += (p1 > 0.f) ? p1 * __log2f(p1) : 0.f;
    #pragma unroll
    for (int o = 16; o > 0; o >>= 1) ent += __shfl_xor_sync(0xffffffffu, ent, o);
    float* pr = g_prob + (size_t)gw * CC;
    pr[lane] = p0;
    if (lane < 16) pr[lane + 32] = p1;
    if (lane == 0) {
        g_lse[gw] = m + __logf(s);
        g_ent2[gw] = ent;
    }
}

// ------------------- K2: crossD, 2 tasks per warp, float4, 3:5 split -------
__global__ void k2_cross() {
    int gw = (blockIdx.x * blockDim.x + threadIdx.x) >> 5;
    int lane = threadIdx.x & 31;
    int group = lane >> 4;
    int gl = lane & 15;
    cudaGridDependencySynchronize();

    int task = gw * 2 + group;
    int b = task / (8 * TP8);
    int rem = task % (8 * TP8);
    int d = rem / TP8 + 1;
    int r4 = rem % TP8;
    int r1 = r4 - 4;
    int r2 = r1 + d;

    const float4* base = (const float4*)(g_prob + (size_t)b * TT * CC);
    float acc = 0.f;
    if (gl < 12) {
        float4 a = (r1 >= 0 && r1 < TT) ? base[r1 * 12 + gl]
                                        : make_float4(0.f, 0.f, 0.f, 0.f);
        float4 c = (r2 >= 0 && r2 < TT) ? base[r2 * 12 + gl]
                                        : make_float4(0.f, 0.f, 0.f, 0.f);
        float sv0 = a.x + c.x, sv1 = a.y + c.y;
        float sv2 = a.z + c.z, sv3 = a.w + c.w;
        float xx0 = 0.5f * sv0 + 1e-32f;
        float xx1 = 0.5f * sv1 + 1e-32f;
        float xx2 = 0.5f * sv2 + 1e-32f;
        float xx3 = 0.5f * sv3 + 1e-32f;
        float lg0, lg1, lg2, lg3;
        if (d <= 3) {
            float2 la = fast_log2_x2(xx0, xx1);
            float2 lb = fast_log2_x2(xx2, xx3);
            lg0 = la.x; lg1 = la.y; lg2 = lb.x; lg3 = lb.y;
        } else {
            lg0 = __log2f(xx0);
            lg1 = __log2f(xx1);
            lg2 = __log2f(xx2);
            lg3 = __log2f(xx3);
        }
        acc = sv0 * lg0 + sv1 * lg1 + sv2 * lg2 + sv3 * lg3;
    }
    #pragma unroll
    for (int o = 8; o > 0; o >>= 1) acc += __shfl_xor_sync(0xffffffffu, acc, o);
    if (gl == 0) g_cross[(b * 8 + (d - 1)) * TP8 + r4] = acc;
}

// ------------------- K45: score + detect + tilesum + barrier + CE/GLC ------
__global__ void k45(const float* __restrict__ fr_logit,
                    const int* __restrict__ transcript,
                    const float* __restrict__ feat,
                    const float* __restrict__ tok_logit,
                    const float* __restrict__ y,
                    float* __restrict__ out) {
    __shared__ __align__(16) unsigned ss[TT];
    __shared__ float sfs[TT];
    __shared__ int scand[NCAND];
    __shared__ int scand2[NCAND];
    __shared__ float scls[NTR * NCAND];
    __shared__ signed char sdir[NCAND * 31];
    __shared__ int s_tr[LL];
    __shared__ float sred[256];
    __shared__ int s_last;
    __shared__ float4 sla4[DD / 4];
    __shared__ float4 stmp[DD / 4];
    __shared__ float s_sim[CC];
    __shared__ int sb[NTR];
    __shared__ int s_m;
    __shared__ float snrm;

    int blk = blockIdx.x;
    int tid = threadIdx.x;
    int lane = tid & 31;
    int w = tid >> 5;

    int b5 = blk / 24;
    int role = blk % 24;
    int btr = (blk < BB) ? blk : b5;
    if (tid < LL) s_tr[tid] = transcript[btr * LL + tid];
    cudaGridDependencySynchronize();       // PDL: wait for k2's g_cross

    // =================== Phase 0: scores (blocks 0..31, old k3) =============
    if (blk < 32) {
        int b = blk >> 3;
        int chunk = blk & 7;
        int t = chunk * 256 + tid;
        float se = 0.f;
        #pragma unroll
        for (int i = 0; i < 4; i++) {
            int r = t - 4 + i;
            se += (r >= 0) ? g_ent2[b * TT + r] : 0.f;
        }
        float cs = 0.f;
        #pragma unroll
        for (int d = 1; d <= 8; d++) {
            const float* crb = g_cross + (size_t)(b * 8 + d - 1) * TP8 + t;
            #pragma unroll
            for (int i = 0; i + d <= 8; i++) {
                float wv = ((i < 4) == ((i + d) < 4)) ? 2.f : -2.f;
                cs += wv * crb[i];
            }
        }
        float sc = (4.f * se + cs) * (1.f / 81.f);
        if (t == 0) sc = -INFINITY;
        g_score[b * TT + t] = sc;
        __threadfence();
        __syncthreads();
        if (tid == 0) atomicAdd(&g_prod[b], 1);
    }

    // =================== Phase 1 ===========================================
    if (blk < BB) {
        int b = blk;
        // wait for this batch's 8 score chunks
        if (tid == 0) {
            while (*((volatile int*)&g_prod[b]) != 8) __nanosleep(32);
            __threadfence();
        }
        __syncthreads();
        for (int t = tid; t < TT; t += 256) {
            float sc = g_score[b * TT + t];
            sfs[t] = sc;
            ss[t] = f2sortable(sc);
        }
        __syncthreads();
        if (tid == 0) g_prod[b] = 0;       // reset for next replay

        if (tid < 32) {
            const uint4* ss4 = (const uint4*)ss;
            unsigned v0 = 0u, v1 = 0u;
            #pragma unroll
            for (int q = 0; q < 8; q++) {
                uint4 a = ss4[lane * 8 + q];
                uint4 c = ss4[(lane + 32) * 8 + q];
                v0 = max(v0, max(max(a.x, a.y), max(a.z, a.w)));
                v1 = max(v1, max(max(c.x, c.y), max(c.z, c.w)));
            }
            for (int it = 0; it < NCAND; it++) {
                unsigned loc = max(v0, v1);
                unsigned mv = __reduce_max_sync(0xffffffffu, loc);
                unsigned m0 = __ballot_sync(0xffffffffu, v0 == mv);
                unsigned m1 = __ballot_sync(0xffffffffu, v1 == mv);
                int seg = m0 ? (__ffs(m0) - 1) : (32 + __ffs(m1) - 1);
                unsigned val = ss[seg * 32 + lane];
                unsigned mk = __ballot_sync(0xffffffffu, val == mv);
                int pick = seg * 32 + (__ffs(mk) - 1);
                if (lane == 0) scand[it] = pick;

                int lo = pick - WINLEN, hi = pick + WINLEN;
                int p0 = lo + lane;
                if (p0 >= 0 && p0 < TT) ss[p0] = 0u;
                int p1 = p0 + 32;
                if (p1 <= hi && p1 < TT) ss[p1] = 0u;
                __syncwarp();

                int slo = (lo < 0 ? 0 : lo) >> 5;
                int shi = ((hi > TT - 1 ? TT - 1 : hi)) >> 5;
                int myseg = (lane >= slo && lane <= shi) ? lane
                          : ((lane + 32 >= slo && lane + 32 <= shi) ? lane + 32 : -1);
                if (myseg >= 0) {
                    const uint4* sp = (const uint4*)(ss + myseg * 32);
                    uint4 a0 = sp[0], a1 = sp[1], a2 = sp[2], a3 = sp[3];
                    uint4 a4 = sp[4], a5 = sp[5], a6 = sp[6], a7 = sp[7];
                    unsigned t0 = max(max(a0.x, a0.y), max(a0.z, a0.w));
                    unsigned t1 = max(max(a1.x, a1.y), max(a1.z, a1.w));
                    unsigned t2 = max(max(a2.x, a2.y), max(a2.z, a2.w));
                    unsigned t3 = max(max(a3.x, a3.y), max(a3.z, a3.w));
                    unsigned t4 = max(max(a4.x, a4.y), max(a4.z, a4.w));
                    unsigned t5 = max(max(a5.x, a5.y), max(a5.z, a5.w));
                    unsigned t6 = max(max(a6.x, a6.y), max(a6.z, a6.w));
                    unsigned t7 = max(max(a7.x, a7.y), max(a7.z, a7.w));
                    unsigned nv = max(max(max(t0, t1), max(t2, t3)),
                                      max(max(t4, t5), max(t6, t7)));
                    if (myseg < 32) v0 = nv; else v1 = nv;
                }
            }
            __syncwarp();
            int c0 = scand[lane];
            int c1 = (lane + 32 < NCAND) ? scand[lane + 32] : 0x7fffffff;
            int r0 = 0, r1 = 0;
            for (int j = 0; j < NCAND; j++) {
                int cj = scand[j];
                r0 += (cj < c0);
                r1 += (cj < c1);
            }
            scand2[r0] = c0;
            if (lane + 32 < NCAND) scand2[r1] = c1;
        }
        __syncthreads();

        const float* pb = g_prob + (size_t)b * TT * CC;
        for (int e = tid; e < NTR * NCAND; e += 256) {
            int tr_i = e / NCAND;
            int n = e % NCAND;
            int cn = scand2[n];
            int ca = s_tr[tr_i], cb = s_tr[tr_i + 1];
            float sacc = 0.f;
            #pragma unroll
            for (int sft = 0; sft < CSZ; sft++) {
                int r = cn + sft - 7;
                if (r >= 0 && r < TT) {
                    float sign = (sft < 7) ? 1.f : -1.f;
                    sacc += sign * (pb[r * CC + ca] - pb[r * CC + cb]);
                }
            }
            scls[e] = sacc * (1.f / 30.f) + sfs[cn];
        }
        __syncthreads();

        if (tid < 32) {
            int j = lane;
            const float FINF = INFINITY;
            bool active = (j < 31);
            float prev;
            if (j == 0) prev = 0.f;
            else if (j == 1) prev = -scls[0 * NCAND + 0];
            else prev = FINF;
            if (active) sdir[j] = (j == 1) ? 1 : 0;
            int ta = j >> 1; if (ta > NTR - 1) ta = NTR - 1;
            bool even = ((j & 1) == 0);
            for (int ii = 1; ii < NCAND; ii++) {
                float dm1 = __shfl_up_sync(0xffffffffu, prev, 1);
                float dm2 = __shfl_up_sync(0xffffffffu, prev, 2);
                if (j < 1) dm1 = FINF;
                if (j < 2) dm2 = FINF;
                float nv; signed char nd;
                if (j >= 2) {
                    if (even) {
                        nv = fminf(prev, dm1);
                        nd = (prev < dm1) ? 0 : 1;
                    } else {
                        nv = -scls[ta * NCAND + ii] + fminf(dm1, dm2);
                        nd = (dm1 < dm2) ? 1 : 2;
                    }
                } else if (j == 0) {
                    nv = (ii < NCAND - NTR) ? 0.f : FINF; nd = 0;
                } else {
                    bool ok = (ii <= NCAND - NTR);
                    nv = ok ? -scls[0 * NCAND + ii] : FINF;
                    nd = ok ? 1 : 0;
                }
                prev = nv;
                if (active) sdir[ii * 31 + j] = nd;
            }
            float p30 = __shfl_sync(0xffffffffu, prev, 30);
            float p29 = __shfl_sync(0xffffffffu, prev, 29);
            if (j == 0) {
                int cj = (p30 < p29) ? 30 : 29;
                int outi[NCAND];
                #pragma unroll
                for (int ii = NCAND - 1; ii >= 0; ii--) {
                    outi[ii] = (cj & 1) ? (cj >> 1) : NTR;
                    cj -= sdir[ii * 31 + cj];
                }
                int res[NTR];
                #pragma unroll
                for (int k2 = 0; k2 < NTR; k2++) res[k2] = 0;
                #pragma unroll
                for (int ii = 0; ii < NCAND; ii++) {
                    int oi = outi[ii];
                    if (oi < NTR) res[oi] = ii;
                }
                #pragma unroll
                for (int k2 = 0; k2 < NTR; k2++)
                    g_bdy[b * NTR + k2] = scand2[res[k2]];
            }
        }
    } else if (blk >= 32 && blk < 32 + 64) {
        // ---- tile sums of fr_feat in the argmax shadow ---------------------
        int bt = blk - 32;
        int b = bt >> 4, tile = bt & 15;
        int q = tid & 127;
        int half = tid >> 7;
        const float4* fb4 = (const float4*)(feat + ((size_t)b * (CC + TT) + CC) * DD);
        int rb = tile * 128;
        float4 a0 = make_float4(0.f, 0.f, 0.f, 0.f);
        float4 a1 = a0, a2 = a0, a3 = a0;
        #pragma unroll 4
        for (int r = 0; r < 128; r += 8) {
            float4 x0 = fb4[(size_t)(rb + r + half) * 128 + q];
            float4 x1 = fb4[(size_t)(rb + r + 2 + half) * 128 + q];
            float4 x2 = fb4[(size_t)(rb + r + 4 + half) * 128 + q];
            float4 x3 = fb4[(size_t)(rb + r + 6 + half) * 128 + q];
            a0.x += x0.x; a0.y += x0.y; a0.z += x0.z; a0.w += x0.w;
            a1.x += x1.x; a1.y += x1.y; a1.z += x1.z; a1.w += x1.w;
            a2.x += x2.x; a2.y += x2.y; a2.z += x2.z; a2.w += x2.w;
            a3.x += x3.x; a3.y += x3.y; a3.z += x3.z; a3.w += x3.w;
        }
        a0.x += a1.x + a2.x + a3.x;
        a0.y += a1.y + a2.y + a3.y;
        a0.z += a1.z + a2.z + a3.z;
        a0.w += a1.w + a2.w + a3.w;
        if (half == 1) stmp[q] = a0;
        __syncthreads();
        if (half == 0) {
            float4 o = stmp[q];
            g_tilesum[(b * 16 + tile) * 128 + q] =
                make_float4(a0.x + o.x, a0.y + o.y, a0.z + o.z, a0.w + o.w);
        }
    }

    // =================== grid barrier (96 blocks) ===========================
    bar45();

    if (blk < BB) {
        __syncthreads();
        if (tid < LL) s_tr[tid] = transcript[b5 * LL + tid];
        __syncthreads();
    }

    // =================== Phase 2: CE + GLC ==================================
    {
        int b = b5;
        if (role < 8) {
            if (tid < NTR) sb[tid] = g_bdy[b * NTR + tid];
            __syncthreads();
            int t = role * 256 + tid;
            int cnt = 0;
            #pragma unroll
            for (int j = 0; j < NTR; j++) cnt += (t >= sb[j]) ? 1 : 0;
            int cid = s_tr[cnt];
            float lce = g_lse[b * TT + t] - fr_logit[(size_t)(b * TT + t) * CC + cid];
            #pragma unroll
            for (int o = 16; o > 0; o >>= 1) lce += __shfl_xor_sync(0xffffffffu, lce, o);
            if (lane == 0) sred[w] = lce;
            __syncthreads();
            if (tid == 0) {
                float s = 0.f;
                #pragma unroll
                for (int ww = 0; ww < 8; ww++) s += sred[ww];
                g_fr32[b * 8 + role] = s;
            }
        } else {
            int k = role - 8;
            if (tid < NTR) sb[tid] = g_bdy[b * NTR + tid];
            __syncthreads();
            if (tid < LL) {
                int v = s_tr[tid];
                int rank = 0;
                #pragma unroll
                for (int i = 0; i < LL; i++) rank += (s_tr[i] < v) ? 1 : 0;
                if (rank == k) s_m = tid;
            }
            __syncthreads();
            int m = s_m;
            int label = s_tr[m];
            int lo = (m == 0) ? 0 : sb[m - 1];
            int hi = (m == LL - 1) ? TT : sb[m];
            int cnt = hi - lo;

            int q = tid & 127;
            int half = tid >> 7;
            const float4* fb4 = (const float4*)(feat + ((size_t)b * (CC + TT) + CC) * DD);
            const float4* ts = g_tilesum + (size_t)(b * 16) * 128;
            float4 a0 = make_float4(0.f, 0.f, 0.f, 0.f);
            float4 a1 = a0, a2 = a0;
            int tlo = (lo + 127) >> 7;
            int thi = hi >> 7;
            if (tlo <= thi) {
                for (int t2 = tlo + half; t2 < thi; t2 += 2) {
                    float4 x = ts[t2 * 128 + q];
                    a0.x += x.x; a0.y += x.y; a0.z += x.z; a0.w += x.w;
                }
                for (int r = lo + half, e = tlo << 7; r < e; r += 2) {
                    float4 x = fb4[(size_t)r * 128 + q];
                    a1.x += x.x; a1.y += x.y; a1.z += x.z; a1.w += x.w;
                }
                for (int r = (thi << 7) + half; r < hi; r += 2) {
                    float4 x = fb4[(size_t)r * 128 + q];
                    a2.x += x.x; a2.y += x.y; a2.z += x.z; a2.w += x.w;
                }
            } else {
                for (int r = lo + half; r < hi; r += 2) {
                    float4 x = fb4[(size_t)r * 128 + q];
                    a0.x += x.x; a0.y += x.y; a0.z += x.z; a0.w += x.w;
                }
            }
            a0.x += a1.x + a2.x;
            a0.y += a1.y + a2.y;
            a0.z += a1.z + a2.z;
            a0.w += a1.w + a2.w;
            if (half == 1) stmp[q] = a0;
            __syncthreads();
            float sq = 0.f;
            float4 mm = make_float4(0.f, 0.f, 0.f, 0.f);
            if (half == 0) {
                float4 o = stmp[q];
                float fc = (cnt > 0) ? (float)cnt : 1.f;
                float inv = 1.f / fc;
                mm.x = (a0.x + o.x) * inv;
                mm.y = (a0.y + o.y) * inv;
                mm.z = (a0.z + o.z) * inv;
                mm.w = (a0.w + o.w) * inv;
                sq = mm.x * mm.x + mm.y * mm.y + mm.z * mm.z + mm.w * mm.w;
            }
            sred[tid] = sq;
            __syncthreads();
            for (int s = 128; s > 0; s >>= 1) {
                if (tid < s) sred[tid] += sred[tid + s];
                __syncthreads();
            }
            if (tid == 0) snrm = 1.f / fmaxf(sqrtf(sred[0]), 1e-12f);
            __syncthreads();
            if (half == 0) {
                float inm = snrm;
                sla4[q] = make_float4(mm.x * inm, mm.y * inm, mm.z * inm, mm.w * inm);
            }
            __syncthreads();

            const float4* tokb4 = (const float4*)(feat + (size_t)b * (CC + TT) * DD);
            #pragma unroll
            for (int jj = 0; jj < 6; jj++) {
                int j = w * 6 + jj;
                const float4* tkr = tokb4 + (size_t)j * 128;
                float dot = 0.f;
                #pragma unroll
                for (int kk = 0; kk < 4; kk++) {
                    int idx = lane + 32 * kk;
                    float4 tv = tkr[idx];
                    float4 lv = sla4[idx];
                    dot += lv.x * tv.x + lv.y * tv.y + lv.z * tv.z + lv.w * tv.w;
                }
                #pragma unroll
                for (int o = 16; o > 0; o >>= 1)
                    dot += __shfl_xor_sync(0xffffffffu, dot, o);
                if (lane == 0)
                    s_sim[j] = dot * g_n2i[b * CC + j];
            }
            __syncthreads();
            if (tid == 0) {
                float mx = -INFINITY;
                for (int j = 0; j < CC; j++) mx = fmaxf(mx, s_sim[j]);
                float se = 0.f;
                for (int j = 0; j < CC; j++) se += __expf(s_sim[j] - mx);
                float lse = mx + __logf(se);
                g_glc_part[b * LL + k] = lse - s_sim[label];
            }
        }
    }

    // ---- last-block final reduction -----------------------------------------
    __syncthreads();
    if (tid == 0) {
        __threadfence();
        int t = atomicAdd(&g_ticket, 1);
        s_last = (t == NB45 - 1) ? 1 : 0;
    }
    __syncthreads();
    if (s_last) {
        float v = 0.f;
        if (tid < BB * CC) {
            float x = tok_logit[tid];
            float yy = y[tid];
            v = -(yy * log_sigmoid_f(x) + (1.f - yy) * log_sigmoid_f(-x));
        }
        sred[tid] = v;
        __syncthreads();
        for (int s = 128; s > 0; s >>= 1) {
            if (tid < s) sred[tid] += sred[tid + s];
            __syncthreads();
        }
        if (tid == 0) {
            float tok = sred[0] / (float)(BB * CC);
            float frs = 0.f;
            for (int i = 0; i < BB * 8; i++) frs += g_fr32[i];
            float fr = frs / (float)(BB * TT);
            float gs = 0.f;
            for (int i = 0; i < BB * LL; i++) gs += g_glc_part[i];
            float glc = gs / (float)(BB * LL);
            out[0] = tok + fr + 0.1f * glc;
            g_ticket = 0;
        }
    }
}

// ------------------- launch (3-node PDL chain) ------------------------------
static void launch_pdl(const void* func, dim3 grid, dim3 block, void** args) {
    cudaLaunchConfig_t cfg = {};
    cfg.gridDim = grid;
    cfg.blockDim = block;
    cfg.stream = 0;
    cudaLaunchAttribute attr[1];
    attr[0].id = cudaLaunchAttributeProgrammaticStreamSerialization;
    attr[0].val.programmaticStreamSerializationAllowed = 1;
    cfg.attrs = attr;
    cfg.numAttrs = 1;
    cudaLaunchKernelExC(&cfg, func, args);
}

extern "C" void kernel_launch(void* const* d_in, const int* in_sizes, int n_in,
                              void* d_out, int out_size) {
    const float* tok_logit  = (const float*)d_in[1];
    const float* fr_logit   = (const float*)d_in[2];
    const int*   transcript = (const int*)d_in[4];
    const float* vid        = (const float*)d_in[5];
    const float* feat       = (const float*)d_in[6];
    float* out = (float*)d_out;

    k1_softmax<<<(BB * TT) / 8 + BB, 256>>>(fr_logit, feat);
    {
        void* args[] = {};
        launch_pdl((const void*)k2_cross, dim3((BB * 8 * TP8) / 16), dim3(256), args);
    }
    {
        void* args[] = {(void*)&fr_logit, (void*)&transcript, (void*)&feat,
                        (void*)&tok_logit, (void*)&vid, (void*)&out};
        launch_pdl((const void*)k45, dim3(NB45), dim3(256), args);
    }
}